// round 1
// baseline (speedup 1.0000x reference)
#include <cuda_runtime.h>
#include <math.h>

#define BATCH 16
#define C_IN 103
#define C_CONV 256
#define N_OUT 103
#define D_OUT 16
#define REC 8343
#define H1_DIM 5562
#define H2_DIM 12514
#define K1 1648
#define CONV_G 2

typedef unsigned long long u64;

// ---------------- static device workspace (no allocations allowed) ----------------
__device__ float g_p[BATCH * C_CONV];
__device__ float g_sq[BATCH * C_CONV];
__device__ float g_Wsum[C_CONV * N_OUT * D_OUT];     // [c][j][o]
__device__ float g_bij[N_OUT * C_CONV];              // [j][c]
__device__ float g_s[N_OUT * BATCH * D_OUT];         // [j][b*16+o]
__device__ float g_f0T[K1 * BATCH];                  // [k][b]
__device__ float g_h1T[H1_DIM * BATCH];              // [k][b]
__device__ float g_h2T[H2_DIM * BATCH];              // [k][b]
__device__ float g_part[3203712];                    // split-K partials (max: 24*8343*16)

// ---------------- reduction helpers ----------------
__device__ __forceinline__ float block_reduce_sum(float v, float* sc) {
    int t = threadIdx.x;
#pragma unroll
    for (int o = 16; o > 0; o >>= 1) v += __shfl_xor_sync(0xffffffffu, v, o);
    if ((t & 31) == 0) sc[t >> 5] = v;
    __syncthreads();
    if (t < 32) {
        float w = (t < 8) ? sc[t] : 0.f;
#pragma unroll
        for (int o = 4; o > 0; o >>= 1) w += __shfl_xor_sync(0xffffffffu, w, o);
        if (t == 0) sc[0] = w;
    }
    __syncthreads();
    float r = sc[0];
    __syncthreads();
    return r;
}

__device__ __forceinline__ float block_reduce_max(float v, float* sc) {
    int t = threadIdx.x;
#pragma unroll
    for (int o = 16; o > 0; o >>= 1) v = fmaxf(v, __shfl_xor_sync(0xffffffffu, v, o));
    if ((t & 31) == 0) sc[t >> 5] = v;
    __syncthreads();
    if (t < 32) {
        float w = (t < 8) ? sc[t] : -1e30f;
#pragma unroll
        for (int o = 4; o > 0; o >>= 1) w = fmaxf(w, __shfl_xor_sync(0xffffffffu, w, o));
        if (t == 0) sc[0] = w;
    }
    __syncthreads();
    float r = sc[0];
    __syncthreads();
    return r;
}

// ---------------- conv 3x3 VALID + relu + spatial mean -> p[b][oc] ----------------
__global__ void k_conv_mean(const float* __restrict__ x, const float* __restrict__ w,
                            const float* __restrict__ bias) {
    __shared__ float sx[C_IN * 81];
    __shared__ float sw[CONV_G * C_IN * 9];
    __shared__ float sacc[CONV_G * 49];
    int b = blockIdx.y;
    int oc0 = blockIdx.x * CONV_G;
    int t = threadIdx.x;
    for (int i = t; i < C_IN * 81; i += blockDim.x) sx[i] = x[b * C_IN * 81 + i];
    for (int i = t; i < CONV_G * C_IN * 9; i += blockDim.x) sw[i] = w[oc0 * C_IN * 9 + i];
    __syncthreads();
    if (t < CONV_G * 49) {
        int ocl = t / 49, pos = t % 49, oy = pos / 7, ox = pos % 7;
        float acc = bias[oc0 + ocl];
        const float* wp = &sw[ocl * C_IN * 9];
        for (int ic = 0; ic < C_IN; ic++) {
            const float* xp = &sx[ic * 81 + oy * 9 + ox];
            const float* wq = &wp[ic * 9];
#pragma unroll
            for (int ky = 0; ky < 3; ky++)
#pragma unroll
                for (int kx = 0; kx < 3; kx++)
                    acc = fmaf(xp[ky * 9 + kx], wq[ky * 3 + kx], acc);
        }
        sacc[t] = fmaxf(acc, 0.f);
    }
    __syncthreads();
    if (t < CONV_G) {
        float s = 0.f;
#pragma unroll
        for (int i = 0; i < 49; i++) s += sacc[t * 49 + i];
        g_p[b * C_CONV + oc0 + t] = s * (1.f / 49.f);
    }
}

// ---------------- squash(p) along channel dim -> sq[b][c] ----------------
__global__ void k_squash_p() {
    __shared__ float sc[8];
    int b = blockIdx.x, t = threadIdx.x;
    float v = g_p[b * C_CONV + t];
    float msq = block_reduce_sum(v * v, sc);
    float mag = sqrtf(msq);
    // mag_sq/(1+mag_sq) * s/mag == s*mag/(1+mag_sq)
    g_sq[b * C_CONV + t] = v * mag / (1.f + msq);
}

// ---------------- Wsum[c][j][o] = sum_i W_caps[c][j][o][i]; also init b_ij ----------------
__global__ void k_wsum(const float* __restrict__ Wc) {
    int e = blockIdx.x * 256 + threadIdx.x;   // exactly 421888 threads
    if (e < N_OUT * C_CONV) g_bij[e] = 1.f;
    const float4* p = (const float4*)(Wc + (size_t)e * 32);
    float s = 0.f;
#pragma unroll
    for (int i = 0; i < 8; i++) {
        float4 v = __ldg(p + i);
        s += (v.x + v.y) + (v.z + v.w);
    }
    g_Wsum[e] = s;
}

// ---------------- routing part 1: softmax(b_ij) over c, s_j = sum_c c*sq*Wsum ----------------
__global__ void k_route1() {
    __shared__ float shw[C_CONV * 17];
    __shared__ float shs[C_CONV * 17];
    __shared__ float shc[C_CONV];
    __shared__ float sc[8];
    int j = blockIdx.x, t = threadIdx.x;
    for (int i = t; i < C_CONV * 16; i += 256) {
        int c = i >> 4, o = i & 15;
        shw[c * 17 + o] = g_Wsum[(c * N_OUT + j) * 16 + o];
    }
    for (int i = t; i < C_CONV * 16; i += 256) {
        int c = i >> 4, bb = i & 15;
        shs[c * 17 + bb] = g_sq[bb * C_CONV + c];
    }
    float bv = g_bij[j * C_CONV + t];
    float m = block_reduce_max(bv, sc);
    float ev = expf(bv - m);
    float ssum = block_reduce_sum(ev, sc);
    shc[t] = ev / ssum;
    __syncthreads();
    for (int i = t; i < C_CONV * 16; i += 256) {
        int c = i >> 4, bb = i & 15;
        shs[c * 17 + bb] *= shc[c];
    }
    __syncthreads();
    int bb = t >> 4, o = t & 15;
    float acc = 0.f;
#pragma unroll 8
    for (int c = 0; c < C_CONV; c++) acc = fmaf(shs[c * 17 + bb], shw[c * 17 + o], acc);
    g_s[j * 256 + t] = acc;
}

// ---------------- routing part 2: squash over j, agreement, b_ij update; epilogue ----------------
__global__ void k_route2(int last, float* __restrict__ dout) {
    __shared__ float shw[C_CONV * 17];
    __shared__ float shq[C_CONV * 17];
    __shared__ float shv[256];
    __shared__ float shba[16];
    int j = blockIdx.x, t = threadIdx.x;
    for (int i = t; i < C_CONV * 16; i += 256) {
        int c = i >> 4, o = i & 15;
        shw[c * 17 + o] = g_Wsum[(c * N_OUT + j) * 16 + o];
    }
    for (int i = t; i < C_CONV * 16; i += 256) {
        int c = i >> 4, bb = i & 15;
        shq[c * 17 + bb] = g_sq[bb * C_CONV + c];
    }
    // deterministic mag_sq over all j (recomputed per block)
    float msq = 0.f;
    for (int jj = 0; jj < N_OUT; jj++) {
        float sv = g_s[jj * 256 + t];
        msq = fmaf(sv, sv, msq);
    }
    float sval = g_s[j * 256 + t];
    float v = sval * sqrtf(msq) / (1.f + msq);
    shv[t] = v;
    __syncthreads();
    // G[c] = sum_b sq[b,c] * sum_o Wsum[c,j,o]*v[b,j,o];  b_ij += G/16
    float g = 0.f;
    for (int b2 = 0; b2 < BATCH; b2++) {
        float d = 0.f;
#pragma unroll
        for (int o = 0; o < 16; o++) d = fmaf(shw[t * 17 + o], shv[b2 * 16 + o], d);
        g = fmaf(shq[t * 17 + b2], d, g);
    }
    g_bij[j * C_CONV + t] += g * (1.f / 16.f);
    if (last) {
        if (t < 16) {
            float r = 0.f;
#pragma unroll
            for (int o = 0; o < 16; o++) { float vv = shv[t * 16 + o]; r = fmaf(vv, vv, r); }
            float ba = sqrtf(r);
            shba[t] = ba;
            dout[t * N_OUT + j] = ba;                 // ba output: [b][j]
        }
        __syncthreads();
        int bb = t >> 4, o = t & 15;
        g_f0T[(j * 16 + o) * 16 + bb] = shv[t] * shba[bb];   // fc input, k-major
    }
}

// ---------------- skinny GEMM (M=16) split-K partial, f32x2 FMA ----------------
__global__ __launch_bounds__(128, 4) void k_fc_part(int insel, const float* __restrict__ W,
                                                    int K, int N, int kchunk) {
    extern __shared__ float sin_[];
    const float* inT = (insel == 0) ? g_f0T : (insel == 1) ? g_h1T : g_h2T;
    int t = threadIdx.x;
    int k0 = blockIdx.y * kchunk;
    int kn = min(K - k0, kchunk);
    for (int i = t; i < kn * 16; i += 128) sin_[i] = inT[k0 * 16 + i];
    __syncthreads();
    int n0 = blockIdx.x * 512 + t;
    u64 acc[4][8];
#pragma unroll
    for (int i = 0; i < 4; i++)
#pragma unroll
        for (int b = 0; b < 8; b++) acc[i][b] = 0ull;
    const float* Wp = W + (size_t)k0 * N;
#pragma unroll 2
    for (int kk = 0; kk < kn; kk++) {
        const u64* ap = (const u64*)(sin_ + kk * 16);
        u64 a0 = ap[0], a1 = ap[1], a2 = ap[2], a3 = ap[3];
        u64 a4 = ap[4], a5 = ap[5], a6 = ap[6], a7 = ap[7];
        const float* wrow = Wp + (size_t)kk * N;
#pragma unroll
        for (int i = 0; i < 4; i++) {
            int n = n0 + i * 128;
            float wv = (n < N) ? __ldg(wrow + n) : 0.f;
            u64 wp_;
            asm("mov.b64 %0,{%1,%1};" : "=l"(wp_) : "f"(wv));
            asm("fma.rn.f32x2 %0,%1,%2,%0;" : "+l"(acc[i][0]) : "l"(a0), "l"(wp_));
            asm("fma.rn.f32x2 %0,%1,%2,%0;" : "+l"(acc[i][1]) : "l"(a1), "l"(wp_));
            asm("fma.rn.f32x2 %0,%1,%2,%0;" : "+l"(acc[i][2]) : "l"(a2), "l"(wp_));
            asm("fma.rn.f32x2 %0,%1,%2,%0;" : "+l"(acc[i][3]) : "l"(a3), "l"(wp_));
            asm("fma.rn.f32x2 %0,%1,%2,%0;" : "+l"(acc[i][4]) : "l"(a4), "l"(wp_));
            asm("fma.rn.f32x2 %0,%1,%2,%0;" : "+l"(acc[i][5]) : "l"(a5), "l"(wp_));
            asm("fma.rn.f32x2 %0,%1,%2,%0;" : "+l"(acc[i][6]) : "l"(a6), "l"(wp_));
            asm("fma.rn.f32x2 %0,%1,%2,%0;" : "+l"(acc[i][7]) : "l"(a7), "l"(wp_));
        }
    }
#pragma unroll
    for (int i = 0; i < 4; i++) {
        int n = n0 + i * 128;
        if (n < N) {
            u64* dst = (u64*)&g_part[((size_t)blockIdx.y * N + n) * 16];
#pragma unroll
            for (int b = 0; b < 8; b++) dst[b] = acc[i][b];
        }
    }
}

// ---------------- split-K reduce + bias; outsel: 1->h1T, 2->h2T, 3->recon in d_out ----------------
__global__ void k_fc_reduce(const float* __restrict__ bias, int outsel, int N, int ks,
                            float* __restrict__ dout) {
    int gid = blockIdx.x * 256 + threadIdx.x;
    if (gid >= N * 16) return;
    int n = gid >> 4, b = gid & 15;
    float s = __ldg(bias + n);
    for (int j = 0; j < ks; j++) s += g_part[((size_t)j * N + n) * 16 + b];
    if (outsel == 3) dout[1648 + b * REC + n] = s;
    else if (outsel == 1) g_h1T[gid] = s;
    else g_h2T[gid] = s;
}

// ---------------- launch ----------------
extern "C" void kernel_launch(void* const* d_in, const int* in_sizes, int n_in,
                              void* d_out, int out_size) {
    const float* x   = (const float*)d_in[0];
    const float* cw  = (const float*)d_in[1];
    const float* cb  = (const float*)d_in[2];
    const float* Wc  = (const float*)d_in[3];
    const float* f1w = (const float*)d_in[4];
    const float* f1b = (const float*)d_in[5];
    const float* f2w = (const float*)d_in[6];
    const float* f2b = (const float*)d_in[7];
    const float* f3w = (const float*)d_in[8];
    const float* f3b = (const float*)d_in[9];
    float* out = (float*)d_out;

    k_conv_mean<<<dim3(C_CONV / CONV_G, BATCH), 128>>>(x, cw, cb);
    k_squash_p<<<BATCH, 256>>>();
    k_wsum<<<1648, 256>>>(Wc);
    for (int it = 0; it < 3; ++it) {
        k_route1<<<N_OUT, 256>>>();
        k_route2<<<N_OUT, 256>>>(it == 2 ? 1 : 0, out);
    }
    // fc1: K=1648 N=5562, ksplit=14 chunk=118
    k_fc_part<<<dim3(11, 14), 128, 118 * 16 * 4>>>(0, f1w, K1, H1_DIM, 118);
    k_fc_reduce<<<348, 256>>>(f1b, 1, H1_DIM, 14, out);
    // fc2: K=5562 N=12514, ksplit=12 chunk=464
    k_fc_part<<<dim3(25, 12), 128, 464 * 16 * 4>>>(1, f2w, H1_DIM, H2_DIM, 464);
    k_fc_reduce<<<783, 256>>>(f2b, 2, H2_DIM, 12, out);
    // fc3: K=12514 N=8343, ksplit=24 chunk=522
    k_fc_part<<<dim3(17, 24), 128, 522 * 16 * 4>>>(2, f3w, H2_DIM, REC, 522);
    k_fc_reduce<<<522, 256>>>(f3b, 3, REC, 24, out);
}

// round 2
// speedup vs baseline: 1.0942x; 1.0942x over previous
#include <cuda_runtime.h>
#include <math.h>

#define BATCH 16
#define C_IN 103
#define C_CONV 256
#define N_OUT 103
#define D_OUT 16
#define REC 8343
#define H1_DIM 5562
#define H2_DIM 12514
#define K1 1648
#define CONV_G 8

typedef unsigned long long u64;

// ---------------- static device workspace ----------------
__device__ float g_p[BATCH * C_CONV];
__device__ float g_WsumJ[N_OUT * C_CONV * D_OUT];    // [j][c][o]
__device__ float g_s[N_OUT * BATCH * D_OUT];         // [j][b*16+o]
__device__ float g_f0T[K1 * BATCH];                  // [k][b]
__device__ float g_h1T[H1_DIM * BATCH];
__device__ float g_h2T[H2_DIM * BATCH];
__device__ float g_part[4500000];
__device__ unsigned g_barcnt = 0;                    // monotonic ticket barrier

// ---------------- helpers ----------------
__device__ __forceinline__ float block_reduce_sum(float v, float* sc) {
    int t = threadIdx.x;
#pragma unroll
    for (int o = 16; o > 0; o >>= 1) v += __shfl_xor_sync(0xffffffffu, v, o);
    if ((t & 31) == 0) sc[t >> 5] = v;
    __syncthreads();
    if (t < 32) {
        float w = (t < 8) ? sc[t] : 0.f;
#pragma unroll
        for (int o = 4; o > 0; o >>= 1) w += __shfl_xor_sync(0xffffffffu, w, o);
        if (t == 0) sc[0] = w;
    }
    __syncthreads();
    float r = sc[0];
    __syncthreads();
    return r;
}

__device__ __forceinline__ float block_reduce_max(float v, float* sc) {
    int t = threadIdx.x;
#pragma unroll
    for (int o = 16; o > 0; o >>= 1) v = fmaxf(v, __shfl_xor_sync(0xffffffffu, v, o));
    if ((t & 31) == 0) sc[t >> 5] = v;
    __syncthreads();
    if (t < 32) {
        float w = (t < 8) ? sc[t] : -1e30f;
#pragma unroll
        for (int o = 4; o > 0; o >>= 1) w = fmaxf(w, __shfl_xor_sync(0xffffffffu, w, o));
        if (t == 0) sc[0] = w;
    }
    __syncthreads();
    float r = sc[0];
    __syncthreads();
    return r;
}

// monotonic-ticket global barrier: no reset, survives graph replays
__device__ __forceinline__ void gbar(unsigned nb) {
    __syncthreads();
    if (threadIdx.x == 0) {
        __threadfence();
        unsigned ticket = atomicAdd(&g_barcnt, 1u);
        unsigned target = (ticket / nb + 1u) * nb;
        while (*(volatile unsigned*)&g_barcnt < target) { __nanosleep(64); }
        __threadfence();
    }
    __syncthreads();
}

// ---------------- conv 3x3 VALID + relu + spatial mean -> p[b][oc] ----------------
__global__ void k_conv_mean(const float* __restrict__ x, const float* __restrict__ w,
                            const float* __restrict__ bias) {
    extern __shared__ float smem[];
    float* sx = smem;                         // 8343
    float* sw = sx + C_IN * 81;               // CONV_G*927
    float* sacc = sw + CONV_G * C_IN * 9;     // CONV_G*49
    int b = blockIdx.y;
    int oc0 = blockIdx.x * CONV_G;
    int t = threadIdx.x;
    for (int i = t; i < C_IN * 81; i += blockDim.x) sx[i] = x[b * C_IN * 81 + i];
    for (int i = t; i < CONV_G * C_IN * 9; i += blockDim.x) sw[i] = w[oc0 * C_IN * 9 + i];
    __syncthreads();
    if (t < CONV_G * 49) {
        int ocl = t / 49, pos = t % 49, oy = pos / 7, ox = pos % 7;
        float acc = bias[oc0 + ocl];
        const float* wp = &sw[ocl * C_IN * 9];
        for (int ic = 0; ic < C_IN; ic++) {
            const float* xp = &sx[ic * 81 + oy * 9 + ox];
            const float* wq = &wp[ic * 9];
#pragma unroll
            for (int ky = 0; ky < 3; ky++)
#pragma unroll
                for (int kx = 0; kx < 3; kx++)
                    acc = fmaf(xp[ky * 9 + kx], wq[ky * 3 + kx], acc);
        }
        sacc[t] = fmaxf(acc, 0.f);
    }
    __syncthreads();
    if (t < CONV_G) {
        float s = 0.f;
#pragma unroll
        for (int i = 0; i < 49; i++) s += sacc[t * 49 + i];
        g_p[b * C_CONV + oc0 + t] = s * (1.f / 49.f);
    }
}

// ---------------- WsumJ[j][c][o] = sum_i W_caps[c][j][o][i] ----------------
__global__ void k_wsum(const float* __restrict__ Wc) {
    int e = blockIdx.x * 256 + threadIdx.x;   // 1648*256 = 421888 = C_CONV*N_OUT*16
    const float4* p = (const float4*)(Wc + (size_t)e * 32);
    float s = 0.f;
#pragma unroll
    for (int i = 0; i < 8; i++) {
        float4 v = __ldg(p + i);
        s += (v.x + v.y) + (v.z + v.w);
    }
    int c = e / 1648;
    int r = e - c * 1648;
    int j = r >> 4, o = r & 15;
    g_WsumJ[((j << 8) + c) * 16 + o] = s;
}

// ---------------- single persistent routing kernel (3 iters) + epilogue ----------------
__global__ void k_route(float* __restrict__ dout) {
    __shared__ float shw[C_CONV * 17];
    __shared__ float shq[C_CONV * 17];
    __shared__ float shcq[C_CONV * 17];
    __shared__ float shc[C_CONV];
    __shared__ float shv[256];
    __shared__ float shba[16];
    __shared__ float sc[8];
    int j = blockIdx.x, t = threadIdx.x;

    // squash(p) over channels, redundantly per block (tiny)
    for (int b = 0; b < BATCH; b++) {
        float v = g_p[b * 256 + t];
        float msq = block_reduce_sum(v * v, sc);
        shq[t * 17 + b] = v * sqrtf(msq) / (1.f + msq);
    }
    // load Wsum slice for this j (coalesced, contiguous 16KB)
    const float4* wj = (const float4*)(g_WsumJ + (size_t)j * 4096);
#pragma unroll
    for (int r = 0; r < 4; r++) {
        int i4 = r * 256 + t;
        float4 v = wj[i4];
        int c = i4 >> 2, o = (i4 & 3) * 4;
        shw[c * 17 + o] = v.x; shw[c * 17 + o + 1] = v.y;
        shw[c * 17 + o + 2] = v.z; shw[c * 17 + o + 3] = v.w;
    }
    float bv = 1.f;     // b_ij for c=t, this j (register-resident)
    __syncthreads();

    int bb = t >> 4, oo = t & 15;
    for (int it = 0; it < 3; it++) {
        // softmax over c
        float m = block_reduce_max(bv, sc);
        float e = expf(bv - m);
        float ssum = block_reduce_sum(e, sc);
        shc[t] = e / ssum;
        __syncthreads();
        for (int i = t; i < 4096; i += 256) {
            int c = i >> 4, b = i & 15;
            shcq[c * 17 + b] = shc[c] * shq[c * 17 + b];
        }
        __syncthreads();
        float acc = 0.f;
#pragma unroll 8
        for (int c = 0; c < 256; c++) acc = fmaf(shcq[c * 17 + bb], shw[c * 17 + oo], acc);
        __stcg(&g_s[j * 256 + t], acc);
        gbar(N_OUT);
        // mag_sq over all j at (b,o)=t
        float msq = 0.f;
#pragma unroll 4
        for (int jj = 0; jj < N_OUT; jj++) {
            float sv = __ldcg(&g_s[jj * 256 + t]);
            msq = fmaf(sv, sv, msq);
        }
        float vv = acc * sqrtf(msq) / (1.f + msq);
        shv[t] = vv;
        __syncthreads();
        if (it < 2) {
            // agreement for c=t: G = sum_b shq[c,b] * sum_o shw[c,o]*v[b,o]
            float g = 0.f;
#pragma unroll
            for (int b2 = 0; b2 < BATCH; b2++) {
                float d = 0.f;
#pragma unroll
                for (int o2 = 0; o2 < 16; o2++) d = fmaf(shw[t * 17 + o2], shv[b2 * 16 + o2], d);
                g = fmaf(shq[t * 17 + b2], d, g);
            }
            bv += g * (1.f / 16.f);
            gbar(N_OUT);   // protect g_s before next iteration overwrites
        }
    }
    // epilogue: ba + fc input (k-major)
    if (t < 16) {
        float r = 0.f;
#pragma unroll
        for (int o2 = 0; o2 < 16; o2++) { float q = shv[t * 16 + o2]; r = fmaf(q, q, r); }
        float ba = sqrtf(r);
        shba[t] = ba;
        dout[t * N_OUT + j] = ba;
    }
    __syncthreads();
    g_f0T[(j * 16 + oo) * 16 + bb] = shv[t] * shba[bb];
}

// ---------------- skinny GEMM (M=16) split-K partials, f32x2 FMA ----------------
template <int NPT>
__global__ __launch_bounds__(256) void k_fc_part(int insel, const float* __restrict__ W,
                                                 int K, int N, int kchunk) {
    extern __shared__ float sin_[];
    const float* inT = (insel == 0) ? g_f0T : (insel == 1) ? g_h1T : g_h2T;
    int t = threadIdx.x;
    int k0 = blockIdx.y * kchunk;
    int kn = min(K - k0, kchunk);
    {
        const float4* src = (const float4*)(inT + (size_t)k0 * 16);
        float4* dst = (float4*)sin_;
        for (int i = t; i < kn * 4; i += 256) dst[i] = src[i];
    }
    __syncthreads();
    int n0 = blockIdx.x * (256 * NPT) + t;
    u64 acc[NPT][8];
#pragma unroll
    for (int i = 0; i < NPT; i++)
#pragma unroll
        for (int b = 0; b < 8; b++) acc[i][b] = 0ull;
    const float* Wp = W + (size_t)k0 * N;
#pragma unroll 4
    for (int kk = 0; kk < kn; kk++) {
        const ulonglong2* ap = (const ulonglong2*)(sin_ + kk * 16);
        ulonglong2 A0 = ap[0], A1 = ap[1], A2 = ap[2], A3 = ap[3];
        const float* wrow = Wp + (size_t)kk * N;
#pragma unroll
        for (int i = 0; i < NPT; i++) {
            int n = n0 + i * 256;
            float wv = (n < N) ? __ldg(wrow + n) : 0.f;
            u64 wp_;
            asm("mov.b64 %0,{%1,%1};" : "=l"(wp_) : "f"(wv));
            asm("fma.rn.f32x2 %0,%1,%2,%0;" : "+l"(acc[i][0]) : "l"(A0.x), "l"(wp_));
            asm("fma.rn.f32x2 %0,%1,%2,%0;" : "+l"(acc[i][1]) : "l"(A0.y), "l"(wp_));
            asm("fma.rn.f32x2 %0,%1,%2,%0;" : "+l"(acc[i][2]) : "l"(A1.x), "l"(wp_));
            asm("fma.rn.f32x2 %0,%1,%2,%0;" : "+l"(acc[i][3]) : "l"(A1.y), "l"(wp_));
            asm("fma.rn.f32x2 %0,%1,%2,%0;" : "+l"(acc[i][4]) : "l"(A2.x), "l"(wp_));
            asm("fma.rn.f32x2 %0,%1,%2,%0;" : "+l"(acc[i][5]) : "l"(A2.y), "l"(wp_));
            asm("fma.rn.f32x2 %0,%1,%2,%0;" : "+l"(acc[i][6]) : "l"(A3.x), "l"(wp_));
            asm("fma.rn.f32x2 %0,%1,%2,%0;" : "+l"(acc[i][7]) : "l"(A3.y), "l"(wp_));
        }
    }
#pragma unroll
    for (int i = 0; i < NPT; i++) {
        int n = n0 + i * 256;
        if (n < N) {
            ulonglong2* dst = (ulonglong2*)&g_part[((size_t)blockIdx.y * N + n) * 16];
            dst[0] = make_ulonglong2(acc[i][0], acc[i][1]);
            dst[1] = make_ulonglong2(acc[i][2], acc[i][3]);
            dst[2] = make_ulonglong2(acc[i][4], acc[i][5]);
            dst[3] = make_ulonglong2(acc[i][6], acc[i][7]);
        }
    }
}

// ---------------- split-K reduce + bias ----------------
__global__ void k_fc_reduce(const float* __restrict__ bias, int outsel, int N, int ks,
                            float* __restrict__ dout) {
    int gid = blockIdx.x * 256 + threadIdx.x;
    if (gid >= N * 16) return;
    int n = gid >> 4, b = gid & 15;
    float s = __ldg(bias + n);
#pragma unroll 4
    for (int j = 0; j < ks; j++) s += g_part[((size_t)j * N + n) * 16 + b];
    if (outsel == 3) dout[1648 + b * REC + n] = s;
    else if (outsel == 1) g_h1T[gid] = s;
    else g_h2T[gid] = s;
}

// ---------------- launch ----------------
extern "C" void kernel_launch(void* const* d_in, const int* in_sizes, int n_in,
                              void* d_out, int out_size) {
    const float* x   = (const float*)d_in[0];
    const float* cw  = (const float*)d_in[1];
    const float* cb  = (const float*)d_in[2];
    const float* Wc  = (const float*)d_in[3];
    const float* f1w = (const float*)d_in[4];
    const float* f1b = (const float*)d_in[5];
    const float* f2w = (const float*)d_in[6];
    const float* f2b = (const float*)d_in[7];
    const float* f3w = (const float*)d_in[8];
    const float* f3b = (const float*)d_in[9];
    float* out = (float*)d_out;

    static int conv_smem_set = 0;
    int conv_smem = (C_IN * 81 + CONV_G * C_IN * 9 + CONV_G * 49) * 4;
    if (!conv_smem_set) {
        cudaFuncSetAttribute(k_conv_mean, cudaFuncAttributeMaxDynamicSharedMemorySize, conv_smem);
        conv_smem_set = 1;
    }

    k_conv_mean<<<dim3(C_CONV / CONV_G, BATCH), 512, conv_smem>>>(x, cw, cb);
    k_wsum<<<1648, 256>>>(Wc);
    k_route<<<N_OUT, 256>>>(out);
    // fc1: K=1648 N=5562, NPT=1: 22 n-blocks, ks=13 (286 blocks), chunk=127
    k_fc_part<1><<<dim3(22, 13), 256, 127 * 64>>>(0, f1w, K1, H1_DIM, 127);
    k_fc_reduce<<<348, 256>>>(f1b, 1, H1_DIM, 13, out);
    // fc2: K=5562 N=12514, NPT=4: 13 n-blocks, ks=22 (286 blocks), chunk=253
    k_fc_part<4><<<dim3(13, 22), 256, 253 * 64>>>(1, f2w, H1_DIM, H2_DIM, 253);
    k_fc_reduce<<<783, 256>>>(f2b, 2, H2_DIM, 22, out);
    // fc3: K=12514 N=8343, NPT=4: 9 n-blocks, ks=32 (288 blocks), chunk=392
    k_fc_part<4><<<dim3(9, 32), 256, 392 * 64>>>(2, f3w, H2_DIM, REC, 392);
    k_fc_reduce<<<522, 256>>>(f3b, 3, REC, 32, out);
}

// round 3
// speedup vs baseline: 1.5509x; 1.4173x over previous
#include <cuda_runtime.h>
#include <math.h>

#define BATCH 16
#define C_IN 103
#define C_CONV 256
#define N_OUT 103
#define D_OUT 16
#define REC 8343
#define H1_DIM 5562
#define H2_DIM 12514
#define K1 1648
#define CONV_G 8

typedef unsigned long long u64;

// ---------------- static device workspace ----------------
__device__ float g_p[BATCH * C_CONV];
__device__ float g_WsumJ[N_OUT * C_CONV * D_OUT];    // [j][c][o]
__device__ float g_s[N_OUT * BATCH * D_OUT];         // [j][b*16+o]
__device__ float g_f0T[K1 * BATCH];                  // [k][b]
__device__ float g_h1T[H1_DIM * BATCH];
__device__ float g_h2T[H2_DIM * BATCH];
__device__ float g_part[3600000];
__device__ unsigned g_barcnt = 0;                    // monotonic ticket barrier

// ---------------- helpers ----------------
__device__ __forceinline__ float block_reduce_sum(float v, float* sc) {
    int t = threadIdx.x;
#pragma unroll
    for (int o = 16; o > 0; o >>= 1) v += __shfl_xor_sync(0xffffffffu, v, o);
    if ((t & 31) == 0) sc[t >> 5] = v;
    __syncthreads();
    if (t < 32) {
        float w = (t < 8) ? sc[t] : 0.f;
#pragma unroll
        for (int o = 4; o > 0; o >>= 1) w += __shfl_xor_sync(0xffffffffu, w, o);
        if (t == 0) sc[0] = w;
    }
    __syncthreads();
    float r = sc[0];
    __syncthreads();
    return r;
}

__device__ __forceinline__ float block_reduce_max(float v, float* sc) {
    int t = threadIdx.x;
#pragma unroll
    for (int o = 16; o > 0; o >>= 1) v = fmaxf(v, __shfl_xor_sync(0xffffffffu, v, o));
    if ((t & 31) == 0) sc[t >> 5] = v;
    __syncthreads();
    if (t < 32) {
        float w = (t < 8) ? sc[t] : -1e30f;
#pragma unroll
        for (int o = 4; o > 0; o >>= 1) w = fmaxf(w, __shfl_xor_sync(0xffffffffu, w, o));
        if (t == 0) sc[0] = w;
    }
    __syncthreads();
    float r = sc[0];
    __syncthreads();
    return r;
}

// monotonic-ticket global barrier: no reset, survives graph replays
__device__ __forceinline__ void gbar(unsigned nb) {
    __syncthreads();
    if (threadIdx.x == 0) {
        __threadfence();
        unsigned ticket = atomicAdd(&g_barcnt, 1u);
        unsigned target = (ticket / nb + 1u) * nb;
        while (*(volatile unsigned*)&g_barcnt < target) { __nanosleep(64); }
        __threadfence();
    }
    __syncthreads();
}

// ---------------- conv 3x3 VALID + relu + spatial mean -> p[b][oc] ----------------
__global__ void k_conv_mean(const float* __restrict__ x, const float* __restrict__ w,
                            const float* __restrict__ bias) {
    extern __shared__ float smem[];
    float* sx = smem;
    float* sw = sx + C_IN * 81;
    float* sacc = sw + CONV_G * C_IN * 9;
    int b = blockIdx.y;
    int oc0 = blockIdx.x * CONV_G;
    int t = threadIdx.x;
    for (int i = t; i < C_IN * 81; i += blockDim.x) sx[i] = x[b * C_IN * 81 + i];
    for (int i = t; i < CONV_G * C_IN * 9; i += blockDim.x) sw[i] = w[oc0 * C_IN * 9 + i];
    __syncthreads();
    if (t < CONV_G * 49) {
        int ocl = t / 49, pos = t % 49, oy = pos / 7, ox = pos % 7;
        float acc = bias[oc0 + ocl];
        const float* wp = &sw[ocl * C_IN * 9];
        for (int ic = 0; ic < C_IN; ic++) {
            const float* xp = &sx[ic * 81 + oy * 9 + ox];
            const float* wq = &wp[ic * 9];
#pragma unroll
            for (int ky = 0; ky < 3; ky++)
#pragma unroll
                for (int kx = 0; kx < 3; kx++)
                    acc = fmaf(xp[ky * 9 + kx], wq[ky * 3 + kx], acc);
        }
        sacc[t] = fmaxf(acc, 0.f);
    }
    __syncthreads();
    if (t < CONV_G) {
        float s = 0.f;
#pragma unroll
        for (int i = 0; i < 49; i++) s += sacc[t * 49 + i];
        g_p[b * C_CONV + oc0 + t] = s * (1.f / 49.f);
    }
}

// ---------------- WsumJ[j][c][o] = sum_i W_caps[c][j][o][i] ----------------
__global__ void k_wsum(const float* __restrict__ Wc) {
    int e = blockIdx.x * 256 + threadIdx.x;   // 421888 = C_CONV*N_OUT*16
    const float4* p = (const float4*)(Wc + (size_t)e * 32);
    float s = 0.f;
#pragma unroll
    for (int i = 0; i < 8; i++) {
        float4 v = __ldg(p + i);
        s += (v.x + v.y) + (v.z + v.w);
    }
    int c = e / 1648;
    int r = e - c * 1648;
    int j = r >> 4, o = r & 15;
    g_WsumJ[((j << 8) + c) * 16 + o] = s;
}

// ---------------- single persistent routing kernel (3 iters) + epilogue ----------------
__global__ void k_route(float* __restrict__ dout) {
    __shared__ float shw[C_CONV * 17];
    __shared__ float shq[C_CONV * 17];
    __shared__ float shcq[C_CONV * 17];
    __shared__ float shc[C_CONV];
    __shared__ float shv[256];
    __shared__ float shba[16];
    __shared__ float sc[8];
    int j = blockIdx.x, t = threadIdx.x;

    for (int b = 0; b < BATCH; b++) {
        float v = g_p[b * 256 + t];
        float msq = block_reduce_sum(v * v, sc);
        shq[t * 17 + b] = v * sqrtf(msq) / (1.f + msq);
    }
    const float4* wj = (const float4*)(g_WsumJ + (size_t)j * 4096);
#pragma unroll
    for (int r = 0; r < 4; r++) {
        int i4 = r * 256 + t;
        float4 v = wj[i4];
        int c = i4 >> 2, o = (i4 & 3) * 4;
        shw[c * 17 + o] = v.x; shw[c * 17 + o + 1] = v.y;
        shw[c * 17 + o + 2] = v.z; shw[c * 17 + o + 3] = v.w;
    }
    float bv = 1.f;
    __syncthreads();

    int bb = t >> 4, oo = t & 15;
    for (int it = 0; it < 3; it++) {
        float m = block_reduce_max(bv, sc);
        float e = expf(bv - m);
        float ssum = block_reduce_sum(e, sc);
        shc[t] = e / ssum;
        __syncthreads();
        for (int i = t; i < 4096; i += 256) {
            int c = i >> 4, b = i & 15;
            shcq[c * 17 + b] = shc[c] * shq[c * 17 + b];
        }
        __syncthreads();
        float acc = 0.f;
#pragma unroll 8
        for (int c = 0; c < 256; c++) acc = fmaf(shcq[c * 17 + bb], shw[c * 17 + oo], acc);
        __stcg(&g_s[j * 256 + t], acc);
        gbar(N_OUT);
        float msq = 0.f;
#pragma unroll 4
        for (int jj = 0; jj < N_OUT; jj++) {
            float sv = __ldcg(&g_s[jj * 256 + t]);
            msq = fmaf(sv, sv, msq);
        }
        float vv = acc * sqrtf(msq) / (1.f + msq);
        shv[t] = vv;
        __syncthreads();
        if (it < 2) {
            float g = 0.f;
#pragma unroll
            for (int b2 = 0; b2 < BATCH; b2++) {
                float d = 0.f;
#pragma unroll
                for (int o2 = 0; o2 < 16; o2++) d = fmaf(shw[t * 17 + o2], shv[b2 * 16 + o2], d);
                g = fmaf(shq[t * 17 + b2], d, g);
            }
            bv += g * (1.f / 16.f);
            gbar(N_OUT);
        }
    }
    if (t < 16) {
        float r = 0.f;
#pragma unroll
        for (int o2 = 0; o2 < 16; o2++) { float q = shv[t * 16 + o2]; r = fmaf(q, q, r); }
        float ba = sqrtf(r);
        shba[t] = ba;
        dout[t * N_OUT + j] = ba;
    }
    __syncthreads();
    g_f0T[(j * 16 + oo) * 16 + bb] = shv[t] * shba[bb];
}

// ---------------- skinny GEMM (M=16) split-K, explicit MLP batching ----------------
#define FMA8(ACC, A0, A1, A2, A3, WP)                                               \
    asm("fma.rn.f32x2 %0,%1,%2,%0;" : "+l"(ACC[0]) : "l"(A0.x), "l"(WP));           \
    asm("fma.rn.f32x2 %0,%1,%2,%0;" : "+l"(ACC[1]) : "l"(A0.y), "l"(WP));           \
    asm("fma.rn.f32x2 %0,%1,%2,%0;" : "+l"(ACC[2]) : "l"(A1.x), "l"(WP));           \
    asm("fma.rn.f32x2 %0,%1,%2,%0;" : "+l"(ACC[3]) : "l"(A1.y), "l"(WP));           \
    asm("fma.rn.f32x2 %0,%1,%2,%0;" : "+l"(ACC[4]) : "l"(A2.x), "l"(WP));           \
    asm("fma.rn.f32x2 %0,%1,%2,%0;" : "+l"(ACC[5]) : "l"(A2.y), "l"(WP));           \
    asm("fma.rn.f32x2 %0,%1,%2,%0;" : "+l"(ACC[6]) : "l"(A3.x), "l"(WP));           \
    asm("fma.rn.f32x2 %0,%1,%2,%0;" : "+l"(ACC[7]) : "l"(A3.y), "l"(WP));

template <int NPT, int U>
__global__ __launch_bounds__(256) void k_fc_part(int insel, const float* __restrict__ W,
                                                 int K, int N, int kchunk) {
    extern __shared__ float sin_[];
    const float* inT = (insel == 0) ? g_f0T : (insel == 1) ? g_h1T : g_h2T;
    int t = threadIdx.x;
    int k0 = blockIdx.y * kchunk;
    int kn = min(K - k0, kchunk);
    {
        const float4* src = (const float4*)(inT + (size_t)k0 * 16);
        float4* dst = (float4*)sin_;
        for (int i = t; i < kn * 4; i += 256) dst[i] = src[i];
    }
    __syncthreads();
    int n0 = blockIdx.x * (256 * NPT) + t;
    int nidx[NPT];
    bool nok[NPT];
#pragma unroll
    for (int i = 0; i < NPT; i++) {
        int n = n0 + i * 256;
        nok[i] = (n < N);
        nidx[i] = nok[i] ? n : 0;       // clamp: loads always valid, result discarded
    }
    u64 acc[NPT][8];
#pragma unroll
    for (int i = 0; i < NPT; i++)
#pragma unroll
        for (int b = 0; b < 8; b++) acc[i][b] = 0ull;
    const float* Wp = W + (size_t)k0 * N;
    int kk = 0;
    for (; kk + U <= kn; kk += U) {
        float w[U][NPT];
        // phase 1: issue all U*NPT independent loads (explicit MLP)
#pragma unroll
        for (int r = 0; r < U; r++) {
            const float* wr = Wp + (size_t)(kk + r) * N;
#pragma unroll
            for (int i = 0; i < NPT; i++) w[r][i] = __ldg(wr + nidx[i]);
        }
        // phase 2: consume
#pragma unroll
        for (int r = 0; r < U; r++) {
            const ulonglong2* ap = (const ulonglong2*)(sin_ + (kk + r) * 16);
            ulonglong2 A0 = ap[0], A1 = ap[1], A2 = ap[2], A3 = ap[3];
#pragma unroll
            for (int i = 0; i < NPT; i++) {
                u64 wp_;
                asm("mov.b64 %0,{%1,%1};" : "=l"(wp_) : "f"(w[r][i]));
                FMA8(acc[i], A0, A1, A2, A3, wp_)
            }
        }
    }
    for (; kk < kn; kk++) {
        const float* wr = Wp + (size_t)kk * N;
        float w1[NPT];
#pragma unroll
        for (int i = 0; i < NPT; i++) w1[i] = __ldg(wr + nidx[i]);
        const ulonglong2* ap = (const ulonglong2*)(sin_ + kk * 16);
        ulonglong2 A0 = ap[0], A1 = ap[1], A2 = ap[2], A3 = ap[3];
#pragma unroll
        for (int i = 0; i < NPT; i++) {
            u64 wp_;
            asm("mov.b64 %0,{%1,%1};" : "=l"(wp_) : "f"(w1[i]));
            FMA8(acc[i], A0, A1, A2, A3, wp_)
        }
    }
#pragma unroll
    for (int i = 0; i < NPT; i++) {
        if (nok[i]) {
            int n = n0 + i * 256;
            ulonglong2* dst = (ulonglong2*)&g_part[((size_t)blockIdx.y * N + n) * 16];
            dst[0] = make_ulonglong2(acc[i][0], acc[i][1]);
            dst[1] = make_ulonglong2(acc[i][2], acc[i][3]);
            dst[2] = make_ulonglong2(acc[i][4], acc[i][5]);
            dst[3] = make_ulonglong2(acc[i][6], acc[i][7]);
        }
    }
}

// ---------------- split-K reduce + bias ----------------
__global__ void k_fc_reduce(const float* __restrict__ bias, int outsel, int N, int ks,
                            float* __restrict__ dout) {
    int gid = blockIdx.x * 256 + threadIdx.x;
    if (gid >= N * 16) return;
    int n = gid >> 4, b = gid & 15;
    float s = __ldg(bias + n);
#pragma unroll 4
    for (int j = 0; j < ks; j++) s += g_part[((size_t)j * N + n) * 16 + b];
    if (outsel == 3) dout[1648 + b * REC + n] = s;
    else if (outsel == 1) g_h1T[gid] = s;
    else g_h2T[gid] = s;
}

// ---------------- launch ----------------
extern "C" void kernel_launch(void* const* d_in, const int* in_sizes, int n_in,
                              void* d_out, int out_size) {
    const float* x   = (const float*)d_in[0];
    const float* cw  = (const float*)d_in[1];
    const float* cb  = (const float*)d_in[2];
    const float* Wc  = (const float*)d_in[3];
    const float* f1w = (const float*)d_in[4];
    const float* f1b = (const float*)d_in[5];
    const float* f2w = (const float*)d_in[6];
    const float* f2b = (const float*)d_in[7];
    const float* f3w = (const float*)d_in[8];
    const float* f3b = (const float*)d_in[9];
    float* out = (float*)d_out;

    static int attr_set = 0;
    int conv_smem = (C_IN * 81 + CONV_G * C_IN * 9 + CONV_G * 49) * 4;
    if (!attr_set) {
        cudaFuncSetAttribute(k_conv_mean, cudaFuncAttributeMaxDynamicSharedMemorySize, conv_smem);
        attr_set = 1;
    }

    k_conv_mean<<<dim3(C_CONV / CONV_G, BATCH), 512, conv_smem>>>(x, cw, cb);
    k_wsum<<<1648, 256>>>(Wc);
    k_route<<<N_OUT, 256>>>(out);
    // fc1: K=1648 N=5562, NPT=1 U=8: 22 n-blocks × ks=20 = 440 blocks (3/SM), chunk=83
    k_fc_part<1, 8><<<dim3(22, 20), 256, 83 * 64>>>(0, f1w, K1, H1_DIM, 83);
    k_fc_reduce<<<348, 256>>>(f1b, 1, H1_DIM, 20, out);
    // fc2: K=5562 N=12514, NPT=2 U=4: 25 n-blocks × ks=17 = 425 blocks, chunk=328
    k_fc_part<2, 4><<<dim3(25, 17), 256, 328 * 64>>>(1, f2w, H1_DIM, H2_DIM, 328);
    k_fc_reduce<<<783, 256>>>(f2b, 2, H2_DIM, 17, out);
    // fc3: K=12514 N=8343, NPT=2 U=4: 17 n-blocks × ks=26 = 442 blocks, chunk=482
    k_fc_part<2, 4><<<dim3(17, 26), 256, 482 * 64>>>(2, f3w, H2_DIM, REC, 482);
    k_fc_reduce<<<522, 256>>>(f3b, 3, REC, 26, out);
}